// round 10
// baseline (speedup 1.0000x reference)
#include <cuda_runtime.h>
#include <cuda_bf16.h>

// Problem constants (fixed by the reference)
#define NN 100000      // N_NODES
#define DD 64          // D_IN == D_OUT
#define NE 1250000     // N_EDGES

#define G_GEMM ((NN + 63) / 64)            // 1563 blocks for the R-GEMM
#define G_SCAT ((NE * 16) / 256)           // 78125 blocks for the scatter

// Scratch accumulator: sum of neighbor features per node (25.6 MB).
// 16B-aligned for red.global.add.v4.f32.
__device__ __align__(16) float g_aggr[NN * DD];

// ---------------------------------------------------------------------------
// Phase 1 (grid-specialized):
//   blocks [0, G_GEMM):      R = x @ W_r + b_l  -> out (f32 scratch, no tanh)
//   blocks [G_GEMM, ...):    scatter-add x[src] into g_aggr[dst] (vector REDG)
// GEMM blocks sit at low bids so they all start in wave 1; scatter blocks
// (L2/atomic-bound) backfill and overlap with the FMA-bound GEMM blocks.
// ---------------------------------------------------------------------------
__global__ void __launch_bounds__(256) phase1_kernel(
        const float* __restrict__ x,
        const int*   __restrict__ src,
        const int*   __restrict__ dst,
        const float* __restrict__ Wr,
        const float* __restrict__ bl,
        float*       __restrict__ out) {
    if (blockIdx.x >= G_GEMM) {
        // ----- scatter part: one thread per (edge, 16B chunk) -----
        long long i = (long long)(blockIdx.x - G_GEMM) * 256 + threadIdx.x;
        if (i >= (long long)NE * 16) return;
        int e = (int)(i >> 4);
        int c = (int)(i & 15);
        int s = __ldg(&src[e]);
        int d = __ldg(&dst[e]);
        float4 v = __ldg((const float4*)x + ((long)s * 16 + c));
        float* p = g_aggr + ((long)d * DD + c * 4);
        asm volatile("red.global.add.v4.f32 [%0], {%1, %2, %3, %4};"
                     :: "l"(p), "f"(v.x), "f"(v.y), "f"(v.z), "f"(v.w)
                     : "memory");
        return;
    }

    // ----- GEMM part: 64x64 tile, 256 threads, 4x4 register tile -----
    __shared__ float sW[DD * DD];
    __shared__ float sA[DD * 65];

    const int tid  = threadIdx.x;
    const int tx   = tid & 15;
    const int ty   = tid >> 4;
    const int row0 = blockIdx.x * 64;

    // load W_r
    {
        const float4* W4 = (const float4*)Wr;
        float4* sW4 = (float4*)sW;
#pragma unroll
        for (int i = 0; i < 4; ++i) sW4[tid + 256 * i] = W4[tid + 256 * i];
    }
    // load x tile transposed: sA[k*65 + row] = x[row0+row][k]
#pragma unroll
    for (int i = 0; i < 4; ++i) {
        int row = (tid >> 4) + i * 16;
        int c4  = tid & 15;
        float4 v = make_float4(0.f, 0.f, 0.f, 0.f);
        if (row0 + row < NN)
            v = __ldg((const float4*)&x[(long)(row0 + row) * DD + c4 * 4]);
        sA[(c4 * 4 + 0) * 65 + row] = v.x;
        sA[(c4 * 4 + 1) * 65 + row] = v.y;
        sA[(c4 * 4 + 2) * 65 + row] = v.z;
        sA[(c4 * 4 + 3) * 65 + row] = v.w;
    }
    __syncthreads();

    float acc[4][4];
#pragma unroll
    for (int i = 0; i < 4; ++i)
#pragma unroll
        for (int j = 0; j < 4; ++j) acc[i][j] = 0.f;

#pragma unroll 8
    for (int k = 0; k < DD; ++k) {
        float4 w = ((const float4*)(sW + k * DD))[tx];
        float a0 = sA[k * 65 + ty * 4 + 0];
        float a1 = sA[k * 65 + ty * 4 + 1];
        float a2 = sA[k * 65 + ty * 4 + 2];
        float a3 = sA[k * 65 + ty * 4 + 3];
        acc[0][0] = fmaf(a0, w.x, acc[0][0]);
        acc[0][1] = fmaf(a0, w.y, acc[0][1]);
        acc[0][2] = fmaf(a0, w.z, acc[0][2]);
        acc[0][3] = fmaf(a0, w.w, acc[0][3]);
        acc[1][0] = fmaf(a1, w.x, acc[1][0]);
        acc[1][1] = fmaf(a1, w.y, acc[1][1]);
        acc[1][2] = fmaf(a1, w.z, acc[1][2]);
        acc[1][3] = fmaf(a1, w.w, acc[1][3]);
        acc[2][0] = fmaf(a2, w.x, acc[2][0]);
        acc[2][1] = fmaf(a2, w.y, acc[2][1]);
        acc[2][2] = fmaf(a2, w.z, acc[2][2]);
        acc[2][3] = fmaf(a2, w.w, acc[2][3]);
        acc[3][0] = fmaf(a3, w.x, acc[3][0]);
        acc[3][1] = fmaf(a3, w.y, acc[3][1]);
        acc[3][2] = fmaf(a3, w.z, acc[3][2]);
        acc[3][3] = fmaf(a3, w.w, acc[3][3]);
    }

    // R = acc + bias -> out (f32 scratch, pre-tanh)
    float4 b = ((const float4*)bl)[tx];
#pragma unroll
    for (int i = 0; i < 4; ++i) {
        int row = row0 + ty * 4 + i;
        if (row < NN) {
            float4 o;
            o.x = acc[i][0] + b.x;
            o.y = acc[i][1] + b.y;
            o.z = acc[i][2] + b.z;
            o.w = acc[i][3] + b.w;
            ((float4*)out)[(long)row * (DD / 4) + tx] = o;
        }
    }
}

// ---------------------------------------------------------------------------
// Phase 2: out = tanh(aggr @ W_l + out)
// ---------------------------------------------------------------------------
__global__ void __launch_bounds__(256) phase2_kernel(
        const float* __restrict__ Wl,
        float*       __restrict__ out) {
    __shared__ float sW[DD * DD];
    __shared__ float sA[DD * 65];

    const int tid  = threadIdx.x;
    const int tx   = tid & 15;
    const int ty   = tid >> 4;
    const int row0 = blockIdx.x * 64;

    {
        const float4* W4 = (const float4*)Wl;
        float4* sW4 = (float4*)sW;
#pragma unroll
        for (int i = 0; i < 4; ++i) sW4[tid + 256 * i] = W4[tid + 256 * i];
    }
#pragma unroll
    for (int i = 0; i < 4; ++i) {
        int row = (tid >> 4) + i * 16;
        int c4  = tid & 15;
        float4 v = make_float4(0.f, 0.f, 0.f, 0.f);
        if (row0 + row < NN)
            v = *(const float4*)&g_aggr[(long)(row0 + row) * DD + c4 * 4];
        sA[(c4 * 4 + 0) * 65 + row] = v.x;
        sA[(c4 * 4 + 1) * 65 + row] = v.y;
        sA[(c4 * 4 + 2) * 65 + row] = v.z;
        sA[(c4 * 4 + 3) * 65 + row] = v.w;
    }
    __syncthreads();

    float acc[4][4];
#pragma unroll
    for (int i = 0; i < 4; ++i)
#pragma unroll
        for (int j = 0; j < 4; ++j) acc[i][j] = 0.f;

#pragma unroll 8
    for (int k = 0; k < DD; ++k) {
        float4 w = ((const float4*)(sW + k * DD))[tx];
        float a0 = sA[k * 65 + ty * 4 + 0];
        float a1 = sA[k * 65 + ty * 4 + 1];
        float a2 = sA[k * 65 + ty * 4 + 2];
        float a3 = sA[k * 65 + ty * 4 + 3];
        acc[0][0] = fmaf(a0, w.x, acc[0][0]);
        acc[0][1] = fmaf(a0, w.y, acc[0][1]);
        acc[0][2] = fmaf(a0, w.z, acc[0][2]);
        acc[0][3] = fmaf(a0, w.w, acc[0][3]);
        acc[1][0] = fmaf(a1, w.x, acc[1][0]);
        acc[1][1] = fmaf(a1, w.y, acc[1][1]);
        acc[1][2] = fmaf(a1, w.z, acc[1][2]);
        acc[1][3] = fmaf(a1, w.w, acc[1][3]);
        acc[2][0] = fmaf(a2, w.x, acc[2][0]);
        acc[2][1] = fmaf(a2, w.y, acc[2][1]);
        acc[2][2] = fmaf(a2, w.z, acc[2][2]);
        acc[2][3] = fmaf(a2, w.w, acc[2][3]);
        acc[3][0] = fmaf(a3, w.x, acc[3][0]);
        acc[3][1] = fmaf(a3, w.y, acc[3][1]);
        acc[3][2] = fmaf(a3, w.z, acc[3][2]);
        acc[3][3] = fmaf(a3, w.w, acc[3][3]);
    }

#pragma unroll
    for (int i = 0; i < 4; ++i) {
        int row = row0 + ty * 4 + i;
        if (row < NN) {
            float4* po = (float4*)out + ((long)row * (DD / 4) + tx);
            float4 r = *po;
            float4 o;
            o.x = tanhf(acc[i][0] + r.x);
            o.y = tanhf(acc[i][1] + r.y);
            o.z = tanhf(acc[i][2] + r.z);
            o.w = tanhf(acc[i][3] + r.w);
            *po = o;
        }
    }
}

// ---------------------------------------------------------------------------
// Launch. Inputs per metadata order:
//   d_in[0] = x          (100000*64 f32)
//   d_in[1] = edge_index (2*1250000 int32)  [row0=src, row1=dst]
//   d_in[2] = W_l (64*64 f32)
//   d_in[3] = b_l (64 f32)
//   d_in[4] = W_r (64*64 f32)
// d_out = 100000*64 f32
// ---------------------------------------------------------------------------
extern "C" void kernel_launch(void* const* d_in, const int* in_sizes, int n_in,
                              void* d_out, int out_size) {
    const float* x   = (const float*)d_in[0];
    const int*   ei  = (const int*)d_in[1];
    const float* Wl  = (const float*)d_in[2];
    const float* bl  = (const float*)d_in[3];
    const float* Wr  = (const float*)d_in[4];
    float*       out = (float*)d_out;

    const int* src = ei;        // edge_index[0]
    const int* dst = ei + NE;   // edge_index[1]

    // 1) zero the accumulator via a memset node (graph-capturable)
    void* aggr_ptr = nullptr;
    cudaGetSymbolAddress(&aggr_ptr, g_aggr);
    cudaMemsetAsync(aggr_ptr, 0, (size_t)NN * DD * sizeof(float));

    // 2) overlapped scatter + R-GEMM
    phase1_kernel<<<G_GEMM + G_SCAT, 256>>>(x, src, dst, Wr, bl, out);

    // 3) out = tanh(aggr @ W_l + out)
    phase2_kernel<<<G_GEMM, 256>>>(Wl, out);
}

// round 12
// speedup vs baseline: 1.3998x; 1.3998x over previous
#include <cuda_runtime.h>
#include <cuda_fp16.h>

// Problem constants (fixed by the reference)
#define NN 100000      // N_NODES
#define DD 64          // D_IN == D_OUT
#define NE 1250000     // N_EDGES

// Two f16 accumulator banks (edge-parity split, summed in f32 later).
// Bank b at offset b*NN*DD halves. 25.6 MB total.
__device__ __align__(16) __half g_aggr2[2 * NN * DD];
// x converted to f16, row = 8 uint4 (64 halves = 128 B). 12.8 MB.
__device__ __align__(16) uint4  g_xh[NN * 8];

// ---------------------------------------------------------------------------
// Kernel 1: convert x (f32) -> g_xh (f16). One thread per 8 floats.
// ---------------------------------------------------------------------------
__global__ void __launch_bounds__(256) conv_kernel(const float4* __restrict__ x4) {
    int i = blockIdx.x * blockDim.x + threadIdx.x;
    if (i >= NN * 8) return;
    float4 a = x4[2 * i];
    float4 b = x4[2 * i + 1];
    __half2 h0 = __floats2half2_rn(a.x, a.y);
    __half2 h1 = __floats2half2_rn(a.z, a.w);
    __half2 h2 = __floats2half2_rn(b.x, b.y);
    __half2 h3 = __floats2half2_rn(b.z, b.w);
    uint4 o;
    o.x = *reinterpret_cast<unsigned*>(&h0);
    o.y = *reinterpret_cast<unsigned*>(&h1);
    o.z = *reinterpret_cast<unsigned*>(&h2);
    o.w = *reinterpret_cast<unsigned*>(&h3);
    g_xh[i] = o;
}

// ---------------------------------------------------------------------------
// Kernel 2: edge scatter-add in f16.
// One thread per (edge, 16B chunk of 8 halves): 8 threads cover an edge's
// 128B f16 row. red.global.add.noftz.v4.f16x2 = 16B per lane-op, so both
// L2 traffic (320MB total) and REDG issue count are HALF the f32 version.
// Edge-parity bank split halves accumulation rounding + atomic contention.
// ---------------------------------------------------------------------------
__global__ void __launch_bounds__(256) scatter_kernel(const int* __restrict__ src,
                                                      const int* __restrict__ dst) {
    long long i = (long long)blockIdx.x * 256 + threadIdx.x;
    if (i >= (long long)NE * 8) return;
    int e = (int)(i >> 3);
    int c = (int)(i & 7);
    int s = __ldg(&src[e]);   // 8 lanes share the address -> broadcast
    int d = __ldg(&dst[e]);
    uint4 v = __ldg(&g_xh[(long)s * 8 + c]);
    __half* p = g_aggr2 + ((size_t)(e & 1) * (NN * DD)) + (size_t)d * DD + c * 8;
    asm volatile("red.global.add.noftz.v4.f16x2 [%0], {%1, %2, %3, %4};"
                 :: "l"(p), "r"(v.x), "r"(v.y), "r"(v.z), "r"(v.w)
                 : "memory");
}

// ---------------------------------------------------------------------------
// Kernel 3: fused  out = tanh((bankA+bankB) @ W_l + b_l + x @ W_r)
// 64x64 tile per block, 256 threads, 4x4 register tile, two passes over
// shared buffers (proven structure from the 123.6us baseline).
// Pass 0 loads the two f16 banks and sums them in f32.
// ---------------------------------------------------------------------------
__global__ void __launch_bounds__(256) fused_gemm_kernel(
        const float* __restrict__ x,
        const float* __restrict__ Wl,
        const float* __restrict__ bl,
        const float* __restrict__ Wr,
        float*       __restrict__ out) {
    __shared__ float sW[DD * DD];        // 16 KB: current weight matrix
    __shared__ float sA[DD * 65];        // 16.25 KB: transposed A tile [k][row]

    const int tid  = threadIdx.x;
    const int tx   = tid & 15;
    const int ty   = tid >> 4;
    const int row0 = blockIdx.x * 64;

    float acc[4][4];
#pragma unroll
    for (int i = 0; i < 4; ++i)
#pragma unroll
        for (int j = 0; j < 4; ++j) acc[i][j] = 0.f;

#pragma unroll
    for (int pass = 0; pass < 2; ++pass) {
        const float* W = pass ? Wr : Wl;

        // load W (64x64 f32 = 1024 float4, 4 per thread)
        {
            const float4* W4 = (const float4*)W;
            float4* sW4 = (float4*)sW;
#pragma unroll
            for (int i = 0; i < 4; ++i) sW4[tid + 256 * i] = W4[tid + 256 * i];
        }
        // load A tile, store transposed: sA[k*65 + row] = A[row0+row][k]
#pragma unroll
        for (int i = 0; i < 4; ++i) {
            int row = (tid >> 4) + i * 16;   // 0..63
            int c4  = tid & 15;              // k-chunk (4 values)
            float4 v = make_float4(0.f, 0.f, 0.f, 0.f);
            if (row0 + row < NN) {
                if (pass == 0) {
                    // aggr = bankA + bankB (f16 -> f32)
                    const uint2* A2 = (const uint2*)g_aggr2;           // 4 halves/uint2
                    const uint2* B2 = A2 + (size_t)NN * 16;            // bank B
                    size_t idx = (size_t)(row0 + row) * 16 + c4;
                    uint2 ua = A2[idx];
                    uint2 ub = B2[idx];
                    float2 a0 = __half22float2(*reinterpret_cast<const __half2*>(&ua.x));
                    float2 a1 = __half22float2(*reinterpret_cast<const __half2*>(&ua.y));
                    float2 b0 = __half22float2(*reinterpret_cast<const __half2*>(&ub.x));
                    float2 b1 = __half22float2(*reinterpret_cast<const __half2*>(&ub.y));
                    v.x = a0.x + b0.x;
                    v.y = a0.y + b0.y;
                    v.z = a1.x + b1.x;
                    v.w = a1.y + b1.y;
                } else {
                    v = __ldg((const float4*)&x[(long)(row0 + row) * DD + c4 * 4]);
                }
            }
            sA[(c4 * 4 + 0) * 65 + row] = v.x;
            sA[(c4 * 4 + 1) * 65 + row] = v.y;
            sA[(c4 * 4 + 2) * 65 + row] = v.z;
            sA[(c4 * 4 + 3) * 65 + row] = v.w;
        }
        __syncthreads();

#pragma unroll 8
        for (int k = 0; k < DD; ++k) {
            float4 w = ((const float4*)(sW + k * DD))[tx];
            float a0 = sA[k * 65 + ty * 4 + 0];
            float a1 = sA[k * 65 + ty * 4 + 1];
            float a2 = sA[k * 65 + ty * 4 + 2];
            float a3 = sA[k * 65 + ty * 4 + 3];
            acc[0][0] = fmaf(a0, w.x, acc[0][0]);
            acc[0][1] = fmaf(a0, w.y, acc[0][1]);
            acc[0][2] = fmaf(a0, w.z, acc[0][2]);
            acc[0][3] = fmaf(a0, w.w, acc[0][3]);
            acc[1][0] = fmaf(a1, w.x, acc[1][0]);
            acc[1][1] = fmaf(a1, w.y, acc[1][1]);
            acc[1][2] = fmaf(a1, w.z, acc[1][2]);
            acc[1][3] = fmaf(a1, w.w, acc[1][3]);
            acc[2][0] = fmaf(a2, w.x, acc[2][0]);
            acc[2][1] = fmaf(a2, w.y, acc[2][1]);
            acc[2][2] = fmaf(a2, w.z, acc[2][2]);
            acc[2][3] = fmaf(a2, w.w, acc[2][3]);
            acc[3][0] = fmaf(a3, w.x, acc[3][0]);
            acc[3][1] = fmaf(a3, w.y, acc[3][1]);
            acc[3][2] = fmaf(a3, w.z, acc[3][2]);
            acc[3][3] = fmaf(a3, w.w, acc[3][3]);
        }
        __syncthreads();   // protect shared before next pass reload
    }

    // epilogue: bias + tanh + store (float4)
    float4 b = ((const float4*)bl)[tx];
#pragma unroll
    for (int i = 0; i < 4; ++i) {
        int row = row0 + ty * 4 + i;
        if (row < NN) {
            float4 o;
            o.x = tanhf(acc[i][0] + b.x);
            o.y = tanhf(acc[i][1] + b.y);
            o.z = tanhf(acc[i][2] + b.z);
            o.w = tanhf(acc[i][3] + b.w);
            ((float4*)out)[(long)row * (DD / 4) + tx] = o;
        }
    }
}

// ---------------------------------------------------------------------------
// Launch. Inputs per metadata order:
//   d_in[0] = x          (100000*64 f32)
//   d_in[1] = edge_index (2*1250000 int32)  [row0=src, row1=dst]
//   d_in[2] = W_l (64*64 f32)
//   d_in[3] = b_l (64 f32)
//   d_in[4] = W_r (64*64 f32)
// d_out = 100000*64 f32
// ---------------------------------------------------------------------------
extern "C" void kernel_launch(void* const* d_in, const int* in_sizes, int n_in,
                              void* d_out, int out_size) {
    const float* x   = (const float*)d_in[0];
    const int*   ei  = (const int*)d_in[1];
    const float* Wl  = (const float*)d_in[2];
    const float* bl  = (const float*)d_in[3];
    const float* Wr  = (const float*)d_in[4];
    float*       out = (float*)d_out;

    const int* src = ei;        // edge_index[0]
    const int* dst = ei + NE;   // edge_index[1]

    // 1) zero both f16 accumulator banks (graph-capturable memset node;
    //    f16 zero == 0x0000)
    void* aggr_ptr = nullptr;
    cudaGetSymbolAddress(&aggr_ptr, g_aggr2);
    cudaMemsetAsync(aggr_ptr, 0, (size_t)2 * NN * DD * sizeof(__half));

    // 2) x -> f16 copy (800K threads)
    conv_kernel<<<(NN * 8 + 255) / 256, 256>>>((const float4*)x);

    // 3) f16 scatter-add: 10M work items (edge x 16B chunk)
    {
        long long items = (long long)NE * 8;
        int blocks = (int)((items + 255) / 256);
        scatter_kernel<<<blocks, 256>>>(src, dst);
    }

    // 4) fused GEMM + bias + tanh (serial — overlap proven not to help)
    fused_gemm_kernel<<<(NN + 63) / 64, 256>>>(x, Wl, bl, Wr, out);
}

// round 13
// speedup vs baseline: 1.4843x; 1.0604x over previous
#include <cuda_runtime.h>
#include <cuda_fp16.h>

// Problem constants (fixed by the reference)
#define NN 100000      // N_NODES
#define DD 64          // D_IN == D_OUT
#define NE 1250000     // N_EDGES

#define G_CONV ((NN * 8 + 255) / 256)          // 3125 blocks: f32->f16 conv
#define G_ZERO ((2 * NN * DD / 8 + 255) / 256) // 6250 blocks: zero 1.6M uint4

// Two f16 accumulator banks (edge-parity split, summed in f32 later). 25.6 MB.
__device__ __align__(16) __half g_aggr2[2 * NN * DD];
// x converted to f16, row = 8 uint4 (64 halves = 128 B). 12.8 MB.
__device__ __align__(16) uint4  g_xh[NN * 8];

// ---------------------------------------------------------------------------
// Kernel 1 (grid-specialized init):
//   blocks [0, G_CONV):            x (f32) -> g_xh (f16)
//   blocks [G_CONV, G_CONV+G_ZERO): zero g_aggr2
// Disjoint buffers; merging removes one launch + serialization bubble.
// ---------------------------------------------------------------------------
__global__ void __launch_bounds__(256) init_kernel(const float4* __restrict__ x4) {
    if (blockIdx.x >= G_CONV) {
        int i = (blockIdx.x - G_CONV) * 256 + threadIdx.x;
        if (i < 2 * NN * DD / 8)
            ((uint4*)g_aggr2)[i] = make_uint4(0u, 0u, 0u, 0u);
        return;
    }
    int i = blockIdx.x * 256 + threadIdx.x;
    if (i >= NN * 8) return;
    float4 a = x4[2 * i];
    float4 b = x4[2 * i + 1];
    __half2 h0 = __floats2half2_rn(a.x, a.y);
    __half2 h1 = __floats2half2_rn(a.z, a.w);
    __half2 h2 = __floats2half2_rn(b.x, b.y);
    __half2 h3 = __floats2half2_rn(b.z, b.w);
    uint4 o;
    o.x = *reinterpret_cast<unsigned*>(&h0);
    o.y = *reinterpret_cast<unsigned*>(&h1);
    o.z = *reinterpret_cast<unsigned*>(&h2);
    o.w = *reinterpret_cast<unsigned*>(&h3);
    g_xh[i] = o;
}

// ---------------------------------------------------------------------------
// Kernel 2: edge scatter-add in f16 (unchanged — at LTS traffic floor).
// 8 threads cover an edge's 128B f16 row; red.global.add.noftz.v4.f16x2.
// Edge-parity bank split halves accumulation rounding + atomic contention.
// ---------------------------------------------------------------------------
__global__ void __launch_bounds__(256) scatter_kernel(const int* __restrict__ src,
                                                      const int* __restrict__ dst) {
    long long i = (long long)blockIdx.x * 256 + threadIdx.x;
    if (i >= (long long)NE * 8) return;
    int e = (int)(i >> 3);
    int c = (int)(i & 7);
    int s = __ldg(&src[e]);   // 8 lanes share the address -> broadcast
    int d = __ldg(&dst[e]);
    uint4 v = __ldg(&g_xh[(long)s * 8 + c]);
    __half* p = g_aggr2 + ((size_t)(e & 1) * (NN * DD)) + (size_t)d * DD + c * 8;
    asm volatile("red.global.add.noftz.v4.f16x2 [%0], {%1, %2, %3, %4};"
                 :: "l"(p), "r"(v.x), "r"(v.y), "r"(v.z), "r"(v.w)
                 : "memory");
}

// ---------------------------------------------------------------------------
// Kernel 3: fused  out = tanh((bankA+bankB) @ W_l + b_l + x @ W_r)
// 64x64 tile per block, 256 threads, 4x4 register tile, two passes.
// sA stored ROW-MAJOR (stride 68, 16B-aligned): load phase is a plain float4
// copy (no transpose STS), inner loop reads A via one broadcast LDS128 per
// 4 k's instead of 4 scalar LDS -> ~3x fewer LDS instructions.
// ---------------------------------------------------------------------------
__global__ void __launch_bounds__(256) fused_gemm_kernel(
        const float* __restrict__ x,
        const float* __restrict__ Wl,
        const float* __restrict__ bl,
        const float* __restrict__ Wr,
        float*       __restrict__ out) {
    __shared__ float sW[DD * DD];        // 16 KB: current weight matrix
    __shared__ float sA[DD * 68];        // 17 KB: row-major A tile [row][k]

    const int tid  = threadIdx.x;
    const int tx   = tid & 15;           // output col group: cols tx*4..tx*4+3
    const int ty   = tid >> 4;           // output row group: rows ty*4..ty*4+3
    const int row0 = blockIdx.x * 64;

    float acc[4][4];
#pragma unroll
    for (int i = 0; i < 4; ++i)
#pragma unroll
        for (int j = 0; j < 4; ++j) acc[i][j] = 0.f;

#pragma unroll
    for (int pass = 0; pass < 2; ++pass) {
        const float* W = pass ? Wr : Wl;

        // load W (64x64 f32 = 1024 float4, 4 per thread)
        {
            const float4* W4 = (const float4*)W;
            float4* sW4 = (float4*)sW;
#pragma unroll
            for (int i = 0; i < 4; ++i) sW4[tid + 256 * i] = W4[tid + 256 * i];
        }
        // load A tile row-major: sA[row][k] — plain float4 copy
#pragma unroll
        for (int i = 0; i < 4; ++i) {
            int row = (tid >> 4) + i * 16;   // 0..63
            int c4  = tid & 15;              // k-chunk (4 floats)
            float4 v = make_float4(0.f, 0.f, 0.f, 0.f);
            if (row0 + row < NN) {
                if (pass == 0) {
                    // aggr = bankA + bankB (f16 -> f32)
                    const uint2* A2 = (const uint2*)g_aggr2;   // 4 halves/uint2
                    const uint2* B2 = A2 + (size_t)NN * 16;    // bank B
                    size_t idx = (size_t)(row0 + row) * 16 + c4;
                    uint2 ua = A2[idx];
                    uint2 ub = B2[idx];
                    float2 a0 = __half22float2(*reinterpret_cast<const __half2*>(&ua.x));
                    float2 a1 = __half22float2(*reinterpret_cast<const __half2*>(&ua.y));
                    float2 b0 = __half22float2(*reinterpret_cast<const __half2*>(&ub.x));
                    float2 b1 = __half22float2(*reinterpret_cast<const __half2*>(&ub.y));
                    v.x = a0.x + b0.x;
                    v.y = a0.y + b0.y;
                    v.z = a1.x + b1.x;
                    v.w = a1.y + b1.y;
                } else {
                    v = __ldg((const float4*)&x[(long)(row0 + row) * DD + c4 * 4]);
                }
            }
            *(float4*)&sA[row * 68 + c4 * 4] = v;
        }
        __syncthreads();

#pragma unroll 4
        for (int k4 = 0; k4 < 16; ++k4) {
            // 4 weight rows (float4 slice at output-col group tx)
            float4 w0 = ((const float4*)(sW + (k4 * 4 + 0) * DD))[tx];
            float4 w1 = ((const float4*)(sW + (k4 * 4 + 1) * DD))[tx];
            float4 w2 = ((const float4*)(sW + (k4 * 4 + 2) * DD))[tx];
            float4 w3 = ((const float4*)(sW + (k4 * 4 + 3) * DD))[tx];
            // 4 A rows x 4 k's — broadcast LDS128 (2 distinct addrs/warp)
#pragma unroll
            for (int i = 0; i < 4; ++i) {
                float4 a = *(const float4*)&sA[(ty * 4 + i) * 68 + k4 * 4];
                acc[i][0] = fmaf(a.x, w0.x, acc[i][0]);
                acc[i][1] = fmaf(a.x, w0.y, acc[i][1]);
                acc[i][2] = fmaf(a.x, w0.z, acc[i][2]);
                acc[i][3] = fmaf(a.x, w0.w, acc[i][3]);
                acc[i][0] = fmaf(a.y, w1.x, acc[i][0]);
                acc[i][1] = fmaf(a.y, w1.y, acc[i][1]);
                acc[i][2] = fmaf(a.y, w1.z, acc[i][2]);
                acc[i][3] = fmaf(a.y, w1.w, acc[i][3]);
                acc[i][0] = fmaf(a.z, w2.x, acc[i][0]);
                acc[i][1] = fmaf(a.z, w2.y, acc[i][1]);
                acc[i][2] = fmaf(a.z, w2.z, acc[i][2]);
                acc[i][3] = fmaf(a.z, w2.w, acc[i][3]);
                acc[i][0] = fmaf(a.w, w3.x, acc[i][0]);
                acc[i][1] = fmaf(a.w, w3.y, acc[i][1]);
                acc[i][2] = fmaf(a.w, w3.z, acc[i][2]);
                acc[i][3] = fmaf(a.w, w3.w, acc[i][3]);
            }
        }
        __syncthreads();   // protect shared before next pass reload
    }

    // epilogue: bias + tanh + store (float4)
    float4 b = ((const float4*)bl)[tx];
#pragma unroll
    for (int i = 0; i < 4; ++i) {
        int row = row0 + ty * 4 + i;
        if (row < NN) {
            float4 o;
            o.x = tanhf(acc[i][0] + b.x);
            o.y = tanhf(acc[i][1] + b.y);
            o.z = tanhf(acc[i][2] + b.z);
            o.w = tanhf(acc[i][3] + b.w);
            ((float4*)out)[(long)row * (DD / 4) + tx] = o;
        }
    }
}

// ---------------------------------------------------------------------------
// Launch. Inputs per metadata order:
//   d_in[0] = x          (100000*64 f32)
//   d_in[1] = edge_index (2*1250000 int32)  [row0=src, row1=dst]
//   d_in[2] = W_l (64*64 f32)
//   d_in[3] = b_l (64 f32)
//   d_in[4] = W_r (64*64 f32)
// d_out = 100000*64 f32
// ---------------------------------------------------------------------------
extern "C" void kernel_launch(void* const* d_in, const int* in_sizes, int n_in,
                              void* d_out, int out_size) {
    const float* x   = (const float*)d_in[0];
    const int*   ei  = (const int*)d_in[1];
    const float* Wl  = (const float*)d_in[2];
    const float* bl  = (const float*)d_in[3];
    const float* Wr  = (const float*)d_in[4];
    float*       out = (float*)d_out;

    const int* src = ei;        // edge_index[0]
    const int* dst = ei + NE;   // edge_index[1]

    // 1) combined zero + f16 conversion
    init_kernel<<<G_CONV + G_ZERO, 256>>>((const float4*)x);

    // 2) f16 scatter-add: 10M work items (edge x 16B chunk)
    {
        long long items = (long long)NE * 8;
        int blocks = (int)((items + 255) / 256);
        scatter_kernel<<<blocks, 256>>>(src, dst);
    }

    // 3) fused GEMM + bias + tanh (serial — overlap proven not to help)
    fused_gemm_kernel<<<(NN + 63) / 64, 256>>>(x, Wl, bl, Wr, out);
}